// round 13
// baseline (speedup 1.0000x reference)
#include <cuda_runtime.h>
#include <cuda_bf16.h>
#include <cstdint>
#include <math.h>

// Problem constants
#define T_SEQ   2048
#define DIM     1024
#define NH      16
#define HD      64
#define QKV3    3072
#define NB      2
#define MROWS   (NB * T_SEQ)     // 4096
#define NCHUNK  (T_SEQ / 64)     // 32

// ---------------- scratch (device globals; allocation-free) ----------------
__device__ __align__(16) __nv_bfloat16 g_x_hi [(size_t)MROWS * DIM];
__device__ __align__(16) __nv_bfloat16 g_x_lo [(size_t)MROWS * DIM];
__device__ __align__(16) __nv_bfloat16 g_wq_hi[(size_t)QKV3 * DIM];
__device__ __align__(16) __nv_bfloat16 g_wq_lo[(size_t)QKV3 * DIM];
__device__ __align__(16) __nv_bfloat16 g_wo_hi[(size_t)DIM * DIM];
__device__ __align__(16) __nv_bfloat16 g_wo_lo[(size_t)DIM * DIM];
__device__ __align__(16) __nv_bfloat16 g_q3_hi[(size_t)MROWS * QKV3];  // split qkv
__device__ __align__(16) __nv_bfloat16 g_q3_lo[(size_t)MROWS * QKV3];
__device__ __align__(16) __nv_bfloat16 g_a_hi [(size_t)MROWS * DIM];   // split attn out
__device__ __align__(16) __nv_bfloat16 g_a_lo [(size_t)MROWS * DIM];

// ---------------- helpers ----------------
__device__ __forceinline__ uint32_t smem_u32(const void* p) {
    uint32_t a;
    asm("{ .reg .u64 t; cvta.to.shared.u64 t, %1; cvt.u32.u64 %0, t; }" : "=r"(a) : "l"(p));
    return a;
}
__device__ __forceinline__ void cp16(uint32_t dst, const void* src) {
    asm volatile("cp.async.cg.shared.global [%0], [%1], 16;" :: "r"(dst), "l"(src) : "memory");
}
#define CP_COMMIT() asm volatile("cp.async.commit_group;" ::: "memory")
#define CP_WAIT0()  asm volatile("cp.async.wait_group 0;" ::: "memory")

__device__ __forceinline__ void ldm_x4(uint32_t* r, uint32_t addr) {
    asm volatile("ldmatrix.sync.aligned.m8n8.x4.shared.b16 {%0,%1,%2,%3}, [%4];"
                 : "=r"(r[0]), "=r"(r[1]), "=r"(r[2]), "=r"(r[3]) : "r"(addr));
}
__device__ __forceinline__ void ldm_x4_t(uint32_t* r, uint32_t addr) {
    asm volatile("ldmatrix.sync.aligned.m8n8.x4.trans.shared.b16 {%0,%1,%2,%3}, [%4];"
                 : "=r"(r[0]), "=r"(r[1]), "=r"(r[2]), "=r"(r[3]) : "r"(addr));
}
__device__ __forceinline__ void mma_bf16(float* d, const uint32_t* a, const uint32_t* b) {
    asm volatile(
        "mma.sync.aligned.m16n8k16.row.col.f32.bf16.bf16.f32 "
        "{%0,%1,%2,%3}, {%4,%5,%6,%7}, {%8,%9}, {%0,%1,%2,%3};"
        : "+f"(d[0]), "+f"(d[1]), "+f"(d[2]), "+f"(d[3])
        : "r"(a[0]), "r"(a[1]), "r"(a[2]), "r"(a[3]), "r"(b[0]), "r"(b[1]));
}
__device__ __forceinline__ uint32_t pkbf2(float a, float b) {
    __nv_bfloat162 t = __floats2bfloat162_rn(a, b);
    return *(uint32_t*)&t;
}
__device__ __forceinline__ void splitpk(float x, float y, uint32_t& hi, uint32_t& lo) {
    const float hx = __bfloat162float(__float2bfloat16_rn(x));
    const float hy = __bfloat162float(__float2bfloat16_rn(y));
    hi = pkbf2(hx, hy);
    lo = pkbf2(x - hx, y - hy);
}

// ---------------------------------------------------------------------------
// fp32 -> bf16 hi/lo split conversion (inputs only)
// ---------------------------------------------------------------------------
__global__ __launch_bounds__(256) void cvt_split(
    const float4* __restrict__ in, __nv_bfloat16* __restrict__ hi,
    __nv_bfloat16* __restrict__ lo, int n4)
{
    int i = blockIdx.x * 256 + threadIdx.x;
    if (i >= n4) return;
    const float4 v = in[i];
    uint2 h, l;
    splitpk(v.x, v.y, h.x, l.x);
    splitpk(v.z, v.w, h.y, l.y);
    *(uint2*)(hi + 4 * (size_t)i) = h;
    *(uint2*)(lo + 4 * (size_t)i) = l;
}

// ---------------------------------------------------------------------------
// Warp-MMA GEMM: C[M,N] = (Ah+Al)[M,K] @ (Bh+Bl)[N,K]^T, 3-term bf16 split.
// 128x128 CTA tile, BK=32, cp.async double buffer.
// 4 warps, 2x2 warp grid, 64x64 warp tile: smem read traffic = 2A + 2B.
// split_out: 0 -> fp32 C; 1 -> bf16 hi/lo Chi/Clo.
// ---------------------------------------------------------------------------
#define BM 128
#define BN 128
#define BK 32
#define ASTR 80
#define MAT_B (128 * ASTR)
#define STAGE_B (4 * MAT_B)
#define GT 128                  // gemm threads

__device__ __forceinline__ void stage_mat(
    const __nv_bfloat16* __restrict__ g, int ld, int r0, int k0,
    uint32_t sdst, int tid)
{
#pragma unroll
    for (int it = 0; it < 4; it++) {
        const int idx = tid + it * GT;      // 0..511 chunks (128 rows x 4)
        const int r = idx >> 2;
        const int c = idx & 3;
        cp16(sdst + r * ASTR + c * 16, g + (size_t)(r0 + r) * ld + k0 + c * 8);
    }
}

__global__ __launch_bounds__(GT) void gemm_mma(
    const __nv_bfloat16* __restrict__ Ah, const __nv_bfloat16* __restrict__ Al,
    const __nv_bfloat16* __restrict__ Bh, const __nv_bfloat16* __restrict__ Bl,
    float* __restrict__ C, __nv_bfloat16* __restrict__ Chi,
    __nv_bfloat16* __restrict__ Clo, int M, int N, int K, int split_out)
{
    extern __shared__ __align__(16) char smem[];
    const uint32_t sb = smem_u32(smem);
    const int tid = threadIdx.x;
    const int wid = tid >> 5;
    const int lane = tid & 31;
    const int warp_m = wid & 1;          // 2 warp-rows of 64
    const int warp_n = wid >> 1;         // 2 warp-cols of 64
    const int row0 = blockIdx.y * BM;
    const int col0 = blockIdx.x * BN;

    float acc[4][8][4];                  // 4 m16-tiles x 8 n8-tiles
#pragma unroll
    for (int mi = 0; mi < 4; mi++)
#pragma unroll
        for (int nj = 0; nj < 8; nj++)
#pragma unroll
            for (int e = 0; e < 4; e++) acc[mi][nj][e] = 0.f;

    stage_mat(Ah, K, row0, 0, sb + 0 * MAT_B, tid);
    stage_mat(Al, K, row0, 0, sb + 1 * MAT_B, tid);
    stage_mat(Bh, K, col0, 0, sb + 2 * MAT_B, tid);
    stage_mat(Bl, K, col0, 0, sb + 3 * MAT_B, tid);
    CP_COMMIT();

    const int NS = K / BK;
    for (int s = 0; s < NS; s++) {
        const int buf = s & 1;
        CP_WAIT0();
        __syncthreads();
        if (s + 1 < NS) {
            const uint32_t nb = sb + (buf ^ 1) * STAGE_B;
            const int k0 = (s + 1) * BK;
            stage_mat(Ah, K, row0, k0, nb + 0 * MAT_B, tid);
            stage_mat(Al, K, row0, k0, nb + 1 * MAT_B, tid);
            stage_mat(Bh, K, col0, k0, nb + 2 * MAT_B, tid);
            stage_mat(Bl, K, col0, k0, nb + 3 * MAT_B, tid);
            CP_COMMIT();
        }

        const uint32_t sAh = sb + buf * STAGE_B + 0 * MAT_B;
        const uint32_t sAl = sb + buf * STAGE_B + 1 * MAT_B;
        const uint32_t sBh = sb + buf * STAGE_B + 2 * MAT_B;
        const uint32_t sBl = sb + buf * STAGE_B + 3 * MAT_B;

#pragma unroll
        for (int ks = 0; ks < 2; ks++) {
            uint32_t ah[4][4], al_[4][4];
#pragma unroll
            for (int mi = 0; mi < 4; mi++) {
                const int m = warp_m * 64 + mi * 16 + (lane & 15);
                const uint32_t off = (uint32_t)m * ASTR + ks * 32 + ((lane >> 4) & 1) * 16;
                ldm_x4(ah[mi], sAh + off);
                ldm_x4(al_[mi], sAl + off);
            }
#pragma unroll
            for (int np = 0; np < 4; np++) {
                const int n = warp_n * 64 + np * 16 + (lane & 7) + ((lane >> 4) & 1) * 8;
                const uint32_t boff = (uint32_t)n * ASTR + ks * 32 + ((lane >> 3) & 1) * 16;
                uint32_t bh[4], bl[4];
                ldm_x4(bh, sBh + boff);
                ldm_x4(bl, sBl + boff);
#pragma unroll
                for (int j = 0; j < 2; j++) {
                    const int nj = np * 2 + j;
#pragma unroll
                    for (int mi = 0; mi < 4; mi++) {
                        mma_bf16(acc[mi][nj], ah[mi],  bh + 2 * j);
                        mma_bf16(acc[mi][nj], ah[mi],  bl + 2 * j);
                        mma_bf16(acc[mi][nj], al_[mi], bh + 2 * j);
                    }
                }
            }
        }
        __syncthreads();
    }

    const int lr = lane >> 2;
    const int lc = (lane & 3) * 2;
#pragma unroll
    for (int mi = 0; mi < 4; mi++) {
#pragma unroll
        for (int nj = 0; nj < 8; nj++) {
            const int r = row0 + warp_m * 64 + mi * 16 + lr;
            const int c = col0 + warp_n * 64 + nj * 8 + lc;
            if (split_out) {
                uint32_t h0, l0, h1, l1;
                splitpk(acc[mi][nj][0], acc[mi][nj][1], h0, l0);
                splitpk(acc[mi][nj][2], acc[mi][nj][3], h1, l1);
                *(uint32_t*)(Chi + (size_t)r * N + c) = h0;
                *(uint32_t*)(Clo + (size_t)r * N + c) = l0;
                *(uint32_t*)(Chi + (size_t)(r + 8) * N + c) = h1;
                *(uint32_t*)(Clo + (size_t)(r + 8) * N + c) = l1;
            } else {
                *(float2*)(C + (size_t)r * N + c) =
                    make_float2(acc[mi][nj][0], acc[mi][nj][1]);
                *(float2*)(C + (size_t)(r + 8) * N + c) =
                    make_float2(acc[mi][nj][2], acc[mi][nj][3]);
            }
        }
    }
}

// ---------------------------------------------------------------------------
// Tensor-core flash attention over 64x64 tiles, K/V double-buffered.
// Mask (causal | same_chunk, 64) == block-lower-triangular with full diagonal
// blocks: query chunk qc attends key chunks 0..qc, NO element masking.
// Smem = 8 mats: [buf0: Kh Kl Vh Vl][buf1: Kh Kl Vh Vl]; Q is staged in
// buf1's Kh/Kl slots during the prologue (read into registers before buf1
// is first written; extra __syncthreads guards the overlap).
// ---------------------------------------------------------------------------
#define AT_STRB 144            // smem row stride bytes (64 bf16 + 16B pad)
#define AT_MAT  (64 * AT_STRB) // 9216 B per matrix
#define AT_NMAT 8

__device__ __forceinline__ void load_kv(
    const __nv_bfloat16* __restrict__ qh_g, const __nv_bfloat16* __restrict__ ql_g,
    size_t rowk, uint32_t mb, int tid)   // mb = base of 4-mat buffer
{
#pragma unroll
    for (int it = 0; it < 4; it++) {
        const int idx = tid + it * 128;
        const int r = idx >> 3, c = idx & 7;
        const size_t gk = rowk + DIM + (size_t)r * QKV3 + c * 8;
        const size_t gv = rowk + 2 * DIM + (size_t)r * QKV3 + c * 8;
        const uint32_t so = (uint32_t)r * AT_STRB + c * 16;
        cp16(mb + 0 * AT_MAT + so, qh_g + gk);   // Kh
        cp16(mb + 1 * AT_MAT + so, ql_g + gk);   // Kl
        cp16(mb + 2 * AT_MAT + so, qh_g + gv);   // Vh
        cp16(mb + 3 * AT_MAT + so, ql_g + gv);   // Vl
    }
}

__global__ __launch_bounds__(128) void attn_mma(
    const __nv_bfloat16* __restrict__ qh_g, const __nv_bfloat16* __restrict__ ql_g,
    __nv_bfloat16* __restrict__ oh_g, __nv_bfloat16* __restrict__ ol_g)
{
    extern __shared__ __align__(16) char smx[];
    const uint32_t sb = smem_u32(smx);

    const int tid = threadIdx.x;
    const int wid = tid >> 5;
    const int lane = tid & 31;
    const int qc = (NCHUNK - 1) - blockIdx.x;   // heavy chunks first
    const int h  = blockIdx.y;
    const int b  = blockIdx.z;

    const size_t rowq  = ((size_t)(b * T_SEQ + qc * 64)) * QKV3 + h * HD;
    const size_t rowk0 = ((size_t)(b * T_SEQ)) * QKV3 + h * HD;   // KEY CHUNK 0 (bug fix)

    // prologue: Q -> buf1's Kh/Kl slots (mats 4,5); K/V(kc=0) -> buf0 (mats 0-3)
    const uint32_t sQh = sb + 4 * AT_MAT, sQl = sb + 5 * AT_MAT;
#pragma unroll
    for (int it = 0; it < 4; it++) {
        const int idx = tid + it * 128;
        const int r = idx >> 3, c = idx & 7;
        const size_t g = rowq + (size_t)r * QKV3 + c * 8;
        const uint32_t so = (uint32_t)r * AT_STRB + c * 16;
        cp16(sQh + so, qh_g + g);
        cp16(sQl + so, ql_g + g);
    }
    load_kv(qh_g, ql_g, rowk0, sb, tid);   // kc=0: K/V of key chunk 0
    CP_COMMIT();

    float o[8][4];
    float mrow[2], lrow[2];
#pragma unroll
    for (int n = 0; n < 8; n++)
#pragma unroll
        for (int e = 0; e < 4; e++) o[n][e] = 0.f;
    mrow[0] = mrow[1] = -1e30f;
    lrow[0] = lrow[1] = 0.f;

    CP_WAIT0();
    __syncthreads();

    // Q A-fragments (resident); then sync before buf1 gets overwritten
    uint32_t qhf[4][4], qlf[4][4];
#pragma unroll
    for (int ks = 0; ks < 4; ks++) {
        const uint32_t off = (uint32_t)(wid * 16 + (lane & 15)) * AT_STRB
                           + ks * 32 + ((lane >> 4) & 1) * 16;
        ldm_x4(qhf[ks], sQh + off);
        ldm_x4(qlf[ks], sQl + off);
    }
    __syncthreads();   // all warps hold Q frags before buf1 loads may land

    for (int kc = 0; kc <= qc; kc++) {
        const int buf = kc & 1;
        if (kc > 0) {            // wait for this buf's loads (issued at kc-1)
            CP_WAIT0();
            __syncthreads();
        }
        if (kc < qc) {           // prefetch next chunk into the other buffer
            const size_t rowk1 = ((size_t)(b * T_SEQ + (kc + 1) * 64)) * QKV3 + h * HD;
            load_kv(qh_g, ql_g, rowk1, sb + (buf ^ 1) * 4 * AT_MAT, tid);
            CP_COMMIT();
        }
        const uint32_t sKh = sb + (buf * 4 + 0) * AT_MAT;
        const uint32_t sKl = sb + (buf * 4 + 1) * AT_MAT;
        const uint32_t sVh = sb + (buf * 4 + 2) * AT_MAT;
        const uint32_t sVl = sb + (buf * 4 + 3) * AT_MAT;

        // ---- S = Q K^T (3-term split) ----
        float s[8][4];
#pragma unroll
        for (int n = 0; n < 8; n++)
#pragma unroll
            for (int e = 0; e < 4; e++) s[n][e] = 0.f;

#pragma unroll
        for (int ks = 0; ks < 4; ks++) {
#pragma unroll
            for (int np = 0; np < 4; np++) {
                const uint32_t ka = (uint32_t)(np * 16 + (lane & 7) + ((lane >> 4) & 1) * 8)
                                  * AT_STRB + ks * 32 + ((lane >> 3) & 1) * 16;
                uint32_t kh[4], kl[4];
                ldm_x4(kh, sKh + ka);
                ldm_x4(kl, sKl + ka);
#pragma unroll
                for (int j = 0; j < 2; j++) {
                    const int nj = np * 2 + j;
                    mma_bf16(s[nj], qhf[ks], kh + 2 * j);
                    mma_bf16(s[nj], qhf[ks], kl + 2 * j);
                    mma_bf16(s[nj], qlf[ks], kh + 2 * j);
                }
            }
        }

        // ---- online softmax ----
#pragma unroll
        for (int n = 0; n < 8; n++)
#pragma unroll
            for (int e = 0; e < 4; e++) s[n][e] *= 0.125f;   // 1/sqrt(64)

#pragma unroll
        for (int i = 0; i < 2; i++) {
            float mx = -1e30f;
#pragma unroll
            for (int n = 0; n < 8; n++)
                mx = fmaxf(mx, fmaxf(s[n][2 * i], s[n][2 * i + 1]));
            mx = fmaxf(mx, __shfl_xor_sync(0xffffffffu, mx, 1));
            mx = fmaxf(mx, __shfl_xor_sync(0xffffffffu, mx, 2));
            const float mnew = fmaxf(mrow[i], mx);
            const float alpha = __expf(mrow[i] - mnew);
            float rs = 0.f;
#pragma unroll
            for (int n = 0; n < 8; n++) {
                s[n][2 * i]     = __expf(s[n][2 * i] - mnew);
                s[n][2 * i + 1] = __expf(s[n][2 * i + 1] - mnew);
                rs += s[n][2 * i] + s[n][2 * i + 1];
            }
            rs += __shfl_xor_sync(0xffffffffu, rs, 1);
            rs += __shfl_xor_sync(0xffffffffu, rs, 2);
            lrow[i] = lrow[i] * alpha + rs;
            mrow[i] = mnew;
#pragma unroll
            for (int n = 0; n < 8; n++) {
                o[n][2 * i]     *= alpha;
                o[n][2 * i + 1] *= alpha;
            }
        }

        // ---- P -> A-fragments (register repack, hi/lo split) ----
        uint32_t ph[4][4], pl[4][4];
#pragma unroll
        for (int t = 0; t < 4; t++) {
            splitpk(s[2 * t][0],     s[2 * t][1],     ph[t][0], pl[t][0]);
            splitpk(s[2 * t][2],     s[2 * t][3],     ph[t][1], pl[t][1]);
            splitpk(s[2 * t + 1][0], s[2 * t + 1][1], ph[t][2], pl[t][2]);
            splitpk(s[2 * t + 1][2], s[2 * t + 1][3], ph[t][3], pl[t][3]);
        }

        // ---- O += P V (3-term split; V B-frags via ldmatrix.trans) ----
#pragma unroll
        for (int t = 0; t < 4; t++) {
#pragma unroll
            for (int dp = 0; dp < 4; dp++) {
                const uint32_t va = (uint32_t)(t * 16 + (lane & 7) + ((lane >> 3) & 1) * 8)
                                  * AT_STRB + dp * 32 + ((lane >> 4) & 1) * 16;
                uint32_t vh[4], vl[4];
                ldm_x4_t(vh, sVh + va);
                ldm_x4_t(vl, sVl + va);
#pragma unroll
                for (int j = 0; j < 2; j++) {
                    const int nj = dp * 2 + j;
                    mma_bf16(o[nj], ph[t], vh + 2 * j);
                    mma_bf16(o[nj], ph[t], vl + 2 * j);
                    mma_bf16(o[nj], pl[t], vh + 2 * j);
                }
            }
        }
        __syncthreads();   // this buf's reads done before it is refilled at kc+2
    }

    // ---- epilogue: normalize, hi/lo split store ----
#pragma unroll
    for (int i = 0; i < 2; i++) {
        const float inv = 1.f / lrow[i];
        const int t = qc * 64 + wid * 16 + (lane >> 2) + i * 8;
        const size_t base = ((size_t)(b * T_SEQ + t)) * DIM + h * HD + (lane & 3) * 2;
#pragma unroll
        for (int n = 0; n < 8; n++) {
            uint32_t hw, lw;
            splitpk(o[n][2 * i] * inv, o[n][2 * i + 1] * inv, hw, lw);
            *(uint32_t*)(oh_g + base + n * 8) = hw;
            *(uint32_t*)(ol_g + base + n * 8) = lw;
        }
    }
}

// ---------------------------------------------------------------------------
extern "C" void kernel_launch(void* const* d_in, const int* in_sizes, int n_in,
                              void* d_out, int out_size)
{
    (void)in_sizes; (void)n_in; (void)out_size;
    const float* x    = (const float*)d_in[0];   // [2,2048,1024]
    const float* Wqkv = (const float*)d_in[1];   // [3072,1024]
    const float* Wout = (const float*)d_in[2];   // [1024,1024]
    float* out = (float*)d_out;                  // [2,2048,1024]

    __nv_bfloat16 *xh, *xl, *wqh, *wql, *woh, *wol, *q3h, *q3l, *ah, *al;
    cudaGetSymbolAddress((void**)&xh,  g_x_hi);  cudaGetSymbolAddress((void**)&xl,  g_x_lo);
    cudaGetSymbolAddress((void**)&wqh, g_wq_hi); cudaGetSymbolAddress((void**)&wql, g_wq_lo);
    cudaGetSymbolAddress((void**)&woh, g_wo_hi); cudaGetSymbolAddress((void**)&wol, g_wo_lo);
    cudaGetSymbolAddress((void**)&q3h, g_q3_hi); cudaGetSymbolAddress((void**)&q3l, g_q3_lo);
    cudaGetSymbolAddress((void**)&ah,  g_a_hi);  cudaGetSymbolAddress((void**)&al,  g_a_lo);

    const int gemm_smem = 2 * STAGE_B;           // 81,920 B
    cudaFuncSetAttribute(gemm_mma, cudaFuncAttributeMaxDynamicSharedMemorySize, gemm_smem);
    const int attn_smem = AT_NMAT * AT_MAT;      // 73,728 B
    cudaFuncSetAttribute(attn_mma, cudaFuncAttributeMaxDynamicSharedMemorySize, attn_smem);

    // 0) split inputs to bf16 hi/lo
    cvt_split<<<(MROWS * DIM / 4 + 255) / 256, 256>>>((const float4*)x, xh, xl, MROWS * DIM / 4);
    cvt_split<<<(QKV3 * DIM / 4 + 255) / 256, 256>>>((const float4*)Wqkv, wqh, wql, QKV3 * DIM / 4);
    cvt_split<<<(DIM * DIM / 4 + 255) / 256, 256>>>((const float4*)Wout, woh, wol, DIM * DIM / 4);

    // 1) QKV projection -> split bf16 output
    {
        dim3 grid(QKV3 / BN, MROWS / BM);
        gemm_mma<<<grid, GT, gemm_smem>>>(xh, xl, wqh, wql,
                                          nullptr, q3h, q3l, MROWS, QKV3, DIM, 1);
    }

    // 2) Tensor-core chunked-causal flash attention -> split bf16 output
    {
        dim3 grid(NCHUNK, NH, NB);
        attn_mma<<<grid, 128, attn_smem>>>(q3h, q3l, ah, al);
    }

    // 3) Output projection -> fp32 final
    {
        dim3 grid(DIM / BN, MROWS / BM);
        gemm_mma<<<grid, GT, gemm_smem>>>(ah, al, woh, wol,
                                          out, nullptr, nullptr, MROWS, DIM, DIM, 0);
    }
}

// round 15
// speedup vs baseline: 1.0188x; 1.0188x over previous
#include <cuda_runtime.h>
#include <cuda_bf16.h>
#include <cstdint>
#include <math.h>

// Problem constants
#define T_SEQ   2048
#define DIM     1024
#define NH      16
#define HD      64
#define QKV3    3072
#define NB      2
#define MROWS   (NB * T_SEQ)     // 4096
#define NCHUNK  (T_SEQ / 64)     // 32

// ---------------- scratch (device globals; allocation-free) ----------------
__device__ __align__(16) __nv_bfloat16 g_x_hi [(size_t)MROWS * DIM];
__device__ __align__(16) __nv_bfloat16 g_x_lo [(size_t)MROWS * DIM];
__device__ __align__(16) __nv_bfloat16 g_wq_hi[(size_t)QKV3 * DIM];
__device__ __align__(16) __nv_bfloat16 g_wq_lo[(size_t)QKV3 * DIM];
__device__ __align__(16) __nv_bfloat16 g_wo_hi[(size_t)DIM * DIM];
__device__ __align__(16) __nv_bfloat16 g_wo_lo[(size_t)DIM * DIM];
__device__ __align__(16) __nv_bfloat16 g_q3_hi[(size_t)MROWS * QKV3];  // split qkv
__device__ __align__(16) __nv_bfloat16 g_q3_lo[(size_t)MROWS * QKV3];
__device__ __align__(16) __nv_bfloat16 g_a_hi [(size_t)MROWS * DIM];   // split attn out
__device__ __align__(16) __nv_bfloat16 g_a_lo [(size_t)MROWS * DIM];

// ---------------- helpers ----------------
__device__ __forceinline__ uint32_t smem_u32(const void* p) {
    uint32_t a;
    asm("{ .reg .u64 t; cvta.to.shared.u64 t, %1; cvt.u32.u64 %0, t; }" : "=r"(a) : "l"(p));
    return a;
}
__device__ __forceinline__ void cp16(uint32_t dst, const void* src) {
    asm volatile("cp.async.cg.shared.global [%0], [%1], 16;" :: "r"(dst), "l"(src) : "memory");
}
#define CP_COMMIT() asm volatile("cp.async.commit_group;" ::: "memory")
#define CP_WAIT0()  asm volatile("cp.async.wait_group 0;" ::: "memory")

__device__ __forceinline__ void ldm_x4(uint32_t* r, uint32_t addr) {
    asm volatile("ldmatrix.sync.aligned.m8n8.x4.shared.b16 {%0,%1,%2,%3}, [%4];"
                 : "=r"(r[0]), "=r"(r[1]), "=r"(r[2]), "=r"(r[3]) : "r"(addr));
}
__device__ __forceinline__ void ldm_x4_t(uint32_t* r, uint32_t addr) {
    asm volatile("ldmatrix.sync.aligned.m8n8.x4.trans.shared.b16 {%0,%1,%2,%3}, [%4];"
                 : "=r"(r[0]), "=r"(r[1]), "=r"(r[2]), "=r"(r[3]) : "r"(addr));
}
__device__ __forceinline__ void mma_bf16(float* d, const uint32_t* a, const uint32_t* b) {
    asm volatile(
        "mma.sync.aligned.m16n8k16.row.col.f32.bf16.bf16.f32 "
        "{%0,%1,%2,%3}, {%4,%5,%6,%7}, {%8,%9}, {%0,%1,%2,%3};"
        : "+f"(d[0]), "+f"(d[1]), "+f"(d[2]), "+f"(d[3])
        : "r"(a[0]), "r"(a[1]), "r"(a[2]), "r"(a[3]), "r"(b[0]), "r"(b[1]));
}
__device__ __forceinline__ uint32_t pkbf2(float a, float b) {
    __nv_bfloat162 t = __floats2bfloat162_rn(a, b);
    return *(uint32_t*)&t;
}
__device__ __forceinline__ void splitpk(float x, float y, uint32_t& hi, uint32_t& lo) {
    const float hx = __bfloat162float(__float2bfloat16_rn(x));
    const float hy = __bfloat162float(__float2bfloat16_rn(y));
    hi = pkbf2(hx, hy);
    lo = pkbf2(x - hx, y - hy);
}

// ---------------------------------------------------------------------------
// fp32 -> bf16 hi/lo split conversion (inputs only)
// ---------------------------------------------------------------------------
__global__ __launch_bounds__(256) void cvt_split(
    const float4* __restrict__ in, __nv_bfloat16* __restrict__ hi,
    __nv_bfloat16* __restrict__ lo, int n4)
{
    int i = blockIdx.x * 256 + threadIdx.x;
    if (i >= n4) return;
    const float4 v = in[i];
    uint2 h, l;
    splitpk(v.x, v.y, h.x, l.x);
    splitpk(v.z, v.w, h.y, l.y);
    *(uint2*)(hi + 4 * (size_t)i) = h;
    *(uint2*)(lo + 4 * (size_t)i) = l;
}

// ---------------------------------------------------------------------------
// Warp-MMA GEMM (measured-good 8-warp layout):
// C[M,N] = (Ah+Al)[M,K] @ (Bh+Bl)[N,K]^T, 3-term bf16 split.
// 128x128 CTA tile, BK=32, cp.async double buffer, 8 warps (32x64 each).
// Split terms issued TERM-MAJOR per np block: same-accumulator reuse
// distance = 4 MMAs (covers HMMA latency; was back-to-back RAW chains).
// split_out: 0 -> fp32 C; 1 -> bf16 hi/lo Chi/Clo.
// ---------------------------------------------------------------------------
#define BM 128
#define BN 128
#define BK 32
#define ASTR 80
#define MAT_B (128 * ASTR)
#define STAGE_B (4 * MAT_B)
#define GT 256                  // gemm threads (8 warps)

__device__ __forceinline__ void stage_mat(
    const __nv_bfloat16* __restrict__ g, int ld, int r0, int k0,
    uint32_t sdst, int tid)
{
#pragma unroll
    for (int it = 0; it < 2; it++) {
        const int idx = tid + it * GT;      // 0..511 chunks (128 rows x 4)
        const int r = idx >> 2;
        const int c = idx & 3;
        cp16(sdst + r * ASTR + c * 16, g + (size_t)(r0 + r) * ld + k0 + c * 8);
    }
}

__global__ __launch_bounds__(GT) void gemm_mma(
    const __nv_bfloat16* __restrict__ Ah, const __nv_bfloat16* __restrict__ Al,
    const __nv_bfloat16* __restrict__ Bh, const __nv_bfloat16* __restrict__ Bl,
    float* __restrict__ C, __nv_bfloat16* __restrict__ Chi,
    __nv_bfloat16* __restrict__ Clo, int M, int N, int K, int split_out)
{
    extern __shared__ __align__(16) char smem[];
    const uint32_t sb = smem_u32(smem);
    const int tid = threadIdx.x;
    const int wid = tid >> 5;
    const int lane = tid & 31;
    const int warp_m = wid & 3;          // 4 warp-rows of 32
    const int warp_n = wid >> 2;         // 2 warp-cols of 64
    const int row0 = blockIdx.y * BM;
    const int col0 = blockIdx.x * BN;

    float acc[2][8][4];
#pragma unroll
    for (int mi = 0; mi < 2; mi++)
#pragma unroll
        for (int nj = 0; nj < 8; nj++)
#pragma unroll
            for (int e = 0; e < 4; e++) acc[mi][nj][e] = 0.f;

    stage_mat(Ah, K, row0, 0, sb + 0 * MAT_B, tid);
    stage_mat(Al, K, row0, 0, sb + 1 * MAT_B, tid);
    stage_mat(Bh, K, col0, 0, sb + 2 * MAT_B, tid);
    stage_mat(Bl, K, col0, 0, sb + 3 * MAT_B, tid);
    CP_COMMIT();

    const int NS = K / BK;
    for (int s = 0; s < NS; s++) {
        const int buf = s & 1;
        CP_WAIT0();
        __syncthreads();
        if (s + 1 < NS) {
            const uint32_t nb = sb + (buf ^ 1) * STAGE_B;
            const int k0 = (s + 1) * BK;
            stage_mat(Ah, K, row0, k0, nb + 0 * MAT_B, tid);
            stage_mat(Al, K, row0, k0, nb + 1 * MAT_B, tid);
            stage_mat(Bh, K, col0, k0, nb + 2 * MAT_B, tid);
            stage_mat(Bl, K, col0, k0, nb + 3 * MAT_B, tid);
            CP_COMMIT();
        }

        const uint32_t sAh = sb + buf * STAGE_B + 0 * MAT_B;
        const uint32_t sAl = sb + buf * STAGE_B + 1 * MAT_B;
        const uint32_t sBh = sb + buf * STAGE_B + 2 * MAT_B;
        const uint32_t sBl = sb + buf * STAGE_B + 3 * MAT_B;

#pragma unroll
        for (int ks = 0; ks < 2; ks++) {
            uint32_t ah[2][4], al_[2][4];
#pragma unroll
            for (int mi = 0; mi < 2; mi++) {
                const int m = warp_m * 32 + mi * 16 + (lane & 15);
                const uint32_t off = (uint32_t)m * ASTR + ks * 32 + ((lane >> 4) & 1) * 16;
                ldm_x4(ah[mi], sAh + off);
                ldm_x4(al_[mi], sAl + off);
            }
#pragma unroll
            for (int np = 0; np < 4; np++) {
                const int n = warp_n * 64 + np * 16 + (lane & 7) + ((lane >> 4) & 1) * 8;
                const uint32_t boff = (uint32_t)n * ASTR + ks * 32 + ((lane >> 3) & 1) * 16;
                uint32_t bh[4], bl[4];
                ldm_x4(bh, sBh + boff);
                ldm_x4(bl, sBl + boff);
                // term-major: same-acc reuse distance = 4 MMAs
#pragma unroll
                for (int j = 0; j < 2; j++)
#pragma unroll
                    for (int mi = 0; mi < 2; mi++)
                        mma_bf16(acc[mi][np * 2 + j], ah[mi],  bh + 2 * j);   // hi*hi
#pragma unroll
                for (int j = 0; j < 2; j++)
#pragma unroll
                    for (int mi = 0; mi < 2; mi++)
                        mma_bf16(acc[mi][np * 2 + j], ah[mi],  bl + 2 * j);   // hi*lo
#pragma unroll
                for (int j = 0; j < 2; j++)
#pragma unroll
                    for (int mi = 0; mi < 2; mi++)
                        mma_bf16(acc[mi][np * 2 + j], al_[mi], bh + 2 * j);   // lo*hi
            }
        }
        __syncthreads();
    }

    const int lr = lane >> 2;
    const int lc = (lane & 3) * 2;
#pragma unroll
    for (int mi = 0; mi < 2; mi++) {
#pragma unroll
        for (int nj = 0; nj < 8; nj++) {
            const int r = row0 + warp_m * 32 + mi * 16 + lr;
            const int c = col0 + warp_n * 64 + nj * 8 + lc;
            if (split_out) {
                uint32_t h0, l0, h1, l1;
                splitpk(acc[mi][nj][0], acc[mi][nj][1], h0, l0);
                splitpk(acc[mi][nj][2], acc[mi][nj][3], h1, l1);
                *(uint32_t*)(Chi + (size_t)r * N + c) = h0;
                *(uint32_t*)(Clo + (size_t)r * N + c) = l0;
                *(uint32_t*)(Chi + (size_t)(r + 8) * N + c) = h1;
                *(uint32_t*)(Clo + (size_t)(r + 8) * N + c) = l1;
            } else {
                *(float2*)(C + (size_t)r * N + c) =
                    make_float2(acc[mi][nj][0], acc[mi][nj][1]);
                *(float2*)(C + (size_t)(r + 8) * N + c) =
                    make_float2(acc[mi][nj][2], acc[mi][nj][3]);
            }
        }
    }
}

// ---------------------------------------------------------------------------
// Tensor-core flash attention over 64x64 tiles, K/V double-buffered.
// Mask (causal | same_chunk, 64) == block-lower-triangular with full diagonal
// blocks. Split-term MMAs issued term-major per np block (distance 2).
// ---------------------------------------------------------------------------
#define AT_STRB 144            // smem row stride bytes (64 bf16 + 16B pad)
#define AT_MAT  (64 * AT_STRB) // 9216 B per matrix
#define AT_NMAT 8

__device__ __forceinline__ void load_kv(
    const __nv_bfloat16* __restrict__ qh_g, const __nv_bfloat16* __restrict__ ql_g,
    size_t rowk, uint32_t mb, int tid)   // mb = base of 4-mat buffer
{
#pragma unroll
    for (int it = 0; it < 4; it++) {
        const int idx = tid + it * 128;
        const int r = idx >> 3, c = idx & 7;
        const size_t gk = rowk + DIM + (size_t)r * QKV3 + c * 8;
        const size_t gv = rowk + 2 * DIM + (size_t)r * QKV3 + c * 8;
        const uint32_t so = (uint32_t)r * AT_STRB + c * 16;
        cp16(mb + 0 * AT_MAT + so, qh_g + gk);   // Kh
        cp16(mb + 1 * AT_MAT + so, ql_g + gk);   // Kl
        cp16(mb + 2 * AT_MAT + so, qh_g + gv);   // Vh
        cp16(mb + 3 * AT_MAT + so, ql_g + gv);   // Vl
    }
}

__global__ __launch_bounds__(128) void attn_mma(
    const __nv_bfloat16* __restrict__ qh_g, const __nv_bfloat16* __restrict__ ql_g,
    __nv_bfloat16* __restrict__ oh_g, __nv_bfloat16* __restrict__ ol_g)
{
    extern __shared__ __align__(16) char smx[];
    const uint32_t sb = smem_u32(smx);

    const int tid = threadIdx.x;
    const int wid = tid >> 5;
    const int lane = tid & 31;
    const int qc = (NCHUNK - 1) - blockIdx.x;   // heavy chunks first
    const int h  = blockIdx.y;
    const int b  = blockIdx.z;

    const size_t rowq  = ((size_t)(b * T_SEQ + qc * 64)) * QKV3 + h * HD;
    const size_t rowk0 = ((size_t)(b * T_SEQ)) * QKV3 + h * HD;   // key chunk 0

    // prologue: Q -> buf1's Kh/Kl slots (mats 4,5); K/V(kc=0) -> buf0 (mats 0-3)
    const uint32_t sQh = sb + 4 * AT_MAT, sQl = sb + 5 * AT_MAT;
#pragma unroll
    for (int it = 0; it < 4; it++) {
        const int idx = tid + it * 128;
        const int r = idx >> 3, c = idx & 7;
        const size_t g = rowq + (size_t)r * QKV3 + c * 8;
        const uint32_t so = (uint32_t)r * AT_STRB + c * 16;
        cp16(sQh + so, qh_g + g);
        cp16(sQl + so, ql_g + g);
    }
    load_kv(qh_g, ql_g, rowk0, sb, tid);
    CP_COMMIT();

    float o[8][4];
    float mrow[2], lrow[2];
#pragma unroll
    for (int n = 0; n < 8; n++)
#pragma unroll
        for (int e = 0; e < 4; e++) o[n][e] = 0.f;
    mrow[0] = mrow[1] = -1e30f;
    lrow[0] = lrow[1] = 0.f;

    CP_WAIT0();
    __syncthreads();

    // Q A-fragments (resident); then sync before buf1 gets overwritten
    uint32_t qhf[4][4], qlf[4][4];
#pragma unroll
    for (int ks = 0; ks < 4; ks++) {
        const uint32_t off = (uint32_t)(wid * 16 + (lane & 15)) * AT_STRB
                           + ks * 32 + ((lane >> 4) & 1) * 16;
        ldm_x4(qhf[ks], sQh + off);
        ldm_x4(qlf[ks], sQl + off);
    }
    __syncthreads();   // all warps hold Q frags before buf1 loads may land

    for (int kc = 0; kc <= qc; kc++) {
        const int buf = kc & 1;
        if (kc > 0) {            // wait for this buf's loads (issued at kc-1)
            CP_WAIT0();
            __syncthreads();
        }
        if (kc < qc) {           // prefetch next chunk into the other buffer
            const size_t rowk1 = ((size_t)(b * T_SEQ + (kc + 1) * 64)) * QKV3 + h * HD;
            load_kv(qh_g, ql_g, rowk1, sb + (buf ^ 1) * 4 * AT_MAT, tid);
            CP_COMMIT();
        }
        const uint32_t sKh = sb + (buf * 4 + 0) * AT_MAT;
        const uint32_t sKl = sb + (buf * 4 + 1) * AT_MAT;
        const uint32_t sVh = sb + (buf * 4 + 2) * AT_MAT;
        const uint32_t sVl = sb + (buf * 4 + 3) * AT_MAT;

        // ---- S = Q K^T (3-term split, term-major per np) ----
        float s[8][4];
#pragma unroll
        for (int n = 0; n < 8; n++)
#pragma unroll
            for (int e = 0; e < 4; e++) s[n][e] = 0.f;

#pragma unroll
        for (int ks = 0; ks < 4; ks++) {
#pragma unroll
            for (int np = 0; np < 4; np++) {
                const uint32_t ka = (uint32_t)(np * 16 + (lane & 7) + ((lane >> 4) & 1) * 8)
                                  * AT_STRB + ks * 32 + ((lane >> 3) & 1) * 16;
                uint32_t kh[4], kl[4];
                ldm_x4(kh, sKh + ka);
                ldm_x4(kl, sKl + ka);
#pragma unroll
                for (int j = 0; j < 2; j++)
                    mma_bf16(s[np * 2 + j], qhf[ks], kh + 2 * j);
#pragma unroll
                for (int j = 0; j < 2; j++)
                    mma_bf16(s[np * 2 + j], qhf[ks], kl + 2 * j);
#pragma unroll
                for (int j = 0; j < 2; j++)
                    mma_bf16(s[np * 2 + j], qlf[ks], kh + 2 * j);
            }
        }

        // ---- online softmax ----
#pragma unroll
        for (int n = 0; n < 8; n++)
#pragma unroll
            for (int e = 0; e < 4; e++) s[n][e] *= 0.125f;   // 1/sqrt(64)

#pragma unroll
        for (int i = 0; i < 2; i++) {
            float mx = -1e30f;
#pragma unroll
            for (int n = 0; n < 8; n++)
                mx = fmaxf(mx, fmaxf(s[n][2 * i], s[n][2 * i + 1]));
            mx = fmaxf(mx, __shfl_xor_sync(0xffffffffu, mx, 1));
            mx = fmaxf(mx, __shfl_xor_sync(0xffffffffu, mx, 2));
            const float mnew = fmaxf(mrow[i], mx);
            const float alpha = __expf(mrow[i] - mnew);
            float rs = 0.f;
#pragma unroll
            for (int n = 0; n < 8; n++) {
                s[n][2 * i]     = __expf(s[n][2 * i] - mnew);
                s[n][2 * i + 1] = __expf(s[n][2 * i + 1] - mnew);
                rs += s[n][2 * i] + s[n][2 * i + 1];
            }
            rs += __shfl_xor_sync(0xffffffffu, rs, 1);
            rs += __shfl_xor_sync(0xffffffffu, rs, 2);
            lrow[i] = lrow[i] * alpha + rs;
            mrow[i] = mnew;
#pragma unroll
            for (int n = 0; n < 8; n++) {
                o[n][2 * i]     *= alpha;
                o[n][2 * i + 1] *= alpha;
            }
        }

        // ---- P -> A-fragments (register repack, hi/lo split) ----
        uint32_t ph[4][4], pl[4][4];
#pragma unroll
        for (int t = 0; t < 4; t++) {
            splitpk(s[2 * t][0],     s[2 * t][1],     ph[t][0], pl[t][0]);
            splitpk(s[2 * t][2],     s[2 * t][3],     ph[t][1], pl[t][1]);
            splitpk(s[2 * t + 1][0], s[2 * t + 1][1], ph[t][2], pl[t][2]);
            splitpk(s[2 * t + 1][2], s[2 * t + 1][3], ph[t][3], pl[t][3]);
        }

        // ---- O += P V (3-term split, term-major per dp) ----
#pragma unroll
        for (int t = 0; t < 4; t++) {
#pragma unroll
            for (int dp = 0; dp < 4; dp++) {
                const uint32_t va = (uint32_t)(t * 16 + (lane & 7) + ((lane >> 3) & 1) * 8)
                                  * AT_STRB + dp * 32 + ((lane >> 4) & 1) * 16;
                uint32_t vh[4], vl[4];
                ldm_x4_t(vh, sVh + va);
                ldm_x4_t(vl, sVl + va);
#pragma unroll
                for (int j = 0; j < 2; j++)
                    mma_bf16(o[dp * 2 + j], ph[t], vh + 2 * j);
#pragma unroll
                for (int j = 0; j < 2; j++)
                    mma_bf16(o[dp * 2 + j], ph[t], vl + 2 * j);
#pragma unroll
                for (int j = 0; j < 2; j++)
                    mma_bf16(o[dp * 2 + j], pl[t], vh + 2 * j);
            }
        }
        __syncthreads();   // this buf's reads done before it is refilled at kc+2
    }

    // ---- epilogue: normalize, hi/lo split store ----
#pragma unroll
    for (int i = 0; i < 2; i++) {
        const float inv = 1.f / lrow[i];
        const int t = qc * 64 + wid * 16 + (lane >> 2) + i * 8;
        const size_t base = ((size_t)(b * T_SEQ + t)) * DIM + h * HD + (lane & 3) * 2;
#pragma unroll
        for (int n = 0; n < 8; n++) {
            uint32_t hw, lw;
            splitpk(o[n][2 * i] * inv, o[n][2 * i + 1] * inv, hw, lw);
            *(uint32_t*)(oh_g + base + n * 8) = hw;
            *(uint32_t*)(ol_g + base + n * 8) = lw;
        }
    }
}

// ---------------------------------------------------------------------------
extern "C" void kernel_launch(void* const* d_in, const int* in_sizes, int n_in,
                              void* d_out, int out_size)
{
    (void)in_sizes; (void)n_in; (void)out_size;
    const float* x    = (const float*)d_in[0];   // [2,2048,1024]
    const float* Wqkv = (const float*)d_in[1];   // [3072,1024]
    const float* Wout = (const float*)d_in[2];   // [1024,1024]
    float* out = (float*)d_out;                  // [2,2048,1024]

    __nv_bfloat16 *xh, *xl, *wqh, *wql, *woh, *wol, *q3h, *q3l, *ah, *al;
    cudaGetSymbolAddress((void**)&xh,  g_x_hi);  cudaGetSymbolAddress((void**)&xl,  g_x_lo);
    cudaGetSymbolAddress((void**)&wqh, g_wq_hi); cudaGetSymbolAddress((void**)&wql, g_wq_lo);
    cudaGetSymbolAddress((void**)&woh, g_wo_hi); cudaGetSymbolAddress((void**)&wol, g_wo_lo);
    cudaGetSymbolAddress((void**)&q3h, g_q3_hi); cudaGetSymbolAddress((void**)&q3l, g_q3_lo);
    cudaGetSymbolAddress((void**)&ah,  g_a_hi);  cudaGetSymbolAddress((void**)&al,  g_a_lo);

    const int gemm_smem = 2 * STAGE_B;           // 81,920 B
    cudaFuncSetAttribute(gemm_mma, cudaFuncAttributeMaxDynamicSharedMemorySize, gemm_smem);
    const int attn_smem = AT_NMAT * AT_MAT;      // 73,728 B
    cudaFuncSetAttribute(attn_mma, cudaFuncAttributeMaxDynamicSharedMemorySize, attn_smem);

    // 0) split inputs to bf16 hi/lo
    cvt_split<<<(MROWS * DIM / 4 + 255) / 256, 256>>>((const float4*)x, xh, xl, MROWS * DIM / 4);
    cvt_split<<<(QKV3 * DIM / 4 + 255) / 256, 256>>>((const float4*)Wqkv, wqh, wql, QKV3 * DIM / 4);
    cvt_split<<<(DIM * DIM / 4 + 255) / 256, 256>>>((const float4*)Wout, woh, wol, DIM * DIM / 4);

    // 1) QKV projection -> split bf16 output
    {
        dim3 grid(QKV3 / BN, MROWS / BM);
        gemm_mma<<<grid, GT, gemm_smem>>>(xh, xl, wqh, wql,
                                          nullptr, q3h, q3l, MROWS, QKV3, DIM, 1);
    }

    // 2) Tensor-core chunked-causal flash attention -> split bf16 output
    {
        dim3 grid(NCHUNK, NH, NB);
        attn_mma<<<grid, 128, attn_smem>>>(q3h, q3l, ah, al);
    }

    // 3) Output projection -> fp32 final
    {
        dim3 grid(DIM / BN, MROWS / BM);
        gemm_mma<<<grid, GT, gemm_smem>>>(ah, al, woh, wol,
                                          out, nullptr, nullptr, MROWS, DIM, DIM, 0);
    }
}